// round 15
// baseline (speedup 1.0000x reference)
#include <cuda_runtime.h>
#include <cuda_fp16.h>
#include <cstdint>

// Problem constants
#define H      2048
#define EI     1024
#define NE     8
#define NT     2048
#define NVOCAB 32000

// GEMM tiling: 128 x 128 tile, BK = 64, 16 warps as 2M x 8N (warp tile 64x16)
#define BM 128
#define BN 128
#define BK 64
#define NTHR 512

// smem per stage: A fp16 [128][64] stride 144B, B f32 [64][128] stride 528B
#define AROWB 144
#define BROWB 528
#define A_BYTES (128 * AROWB)            // 18432
#define B_BYTES (64 * BROWB)             // 33792
#define STAGE_BYTES (A_BYTES + B_BYTES)  // 52224
#define NSTAGE 3
#define TOK_OFF (NSTAGE * STAGE_BYTES)   // 156672
#define SMEM_BYTES (TOK_OFF + BM * 4)    // 157184 -> 1 CTA/SM

// Scratch (20 MB)
__device__ __half g_xh[(size_t)NT * H];
__device__ __half g_gu[(size_t)NT * H];
__device__ __half g_h[(size_t)NT * EI];
__device__ int    g_perm[NT];
__device__ int    g_cnt[NE];
__device__ int    g_off[NE];

// ---------------------------------------------------------------------------
// helpers
// ---------------------------------------------------------------------------
__device__ __forceinline__ float silu(float x) { return x / (1.0f + __expf(-x)); }

__device__ __forceinline__ void cp_async16(void* dst_smem, const void* src) {
    uint32_t dst = (uint32_t)__cvta_generic_to_shared(dst_smem);
    asm volatile("cp.async.cg.shared.global [%0], [%1], 16;\n" :: "r"(dst), "l"(src));
}
#define CP_COMMIT() asm volatile("cp.async.commit_group;\n")
#define CP_WAIT(n)  asm volatile("cp.async.wait_group %0;\n" :: "n"(n))

__device__ __forceinline__ void mma_f16(float* d, const uint32_t* a, const uint32_t* b) {
    asm volatile(
        "mma.sync.aligned.m16n8k16.row.col.f32.f16.f16.f32 "
        "{%0,%1,%2,%3}, {%4,%5,%6,%7}, {%8,%9}, {%0,%1,%2,%3};"
        : "+f"(d[0]), "+f"(d[1]), "+f"(d[2]), "+f"(d[3])
        : "r"(a[0]), "r"(a[1]), "r"(a[2]), "r"(a[3]), "r"(b[0]), "r"(b[1]));
}

__device__ __forceinline__ void ldsm_x4(uint32_t* r, uint32_t addr) {
    asm volatile("ldmatrix.sync.aligned.m8n8.x4.shared.b16 {%0,%1,%2,%3}, [%4];"
                 : "=r"(r[0]), "=r"(r[1]), "=r"(r[2]), "=r"(r[3]) : "r"(addr));
}

__device__ __forceinline__ uint32_t pack2h(float lo, float hi) {
    __half2 h = __floats2half2_rn(lo, hi);
    return *reinterpret_cast<uint32_t*>(&h);
}

// ---------------------------------------------------------------------------
// prep: blocks [0, NXB) convert x -> fp16; block NXB does routing.
// ---------------------------------------------------------------------------
#define RT_THREADS 256
#define RT_PER_THR (NT / RT_THREADS)
#define NXB ((NT * H / 8) / 256)

__global__ void prep_kernel(const float* __restrict__ x,
                            const int* __restrict__ token_ids) {
    if (blockIdx.x < NXB) {
        size_t i = ((size_t)blockIdx.x * 256 + threadIdx.x) * 8;
        float4 v0 = *reinterpret_cast<const float4*>(x + i);
        float4 v1 = *reinterpret_cast<const float4*>(x + i + 4);
        uint4 u;
        u.x = pack2h(v0.x, v0.y);
        u.y = pack2h(v0.z, v0.w);
        u.z = pack2h(v1.x, v1.y);
        u.w = pack2h(v1.z, v1.w);
        *reinterpret_cast<uint4*>(g_xh + i) = u;
        return;
    }

    __shared__ int s_hist[RT_THREADS][NE];
    __shared__ int s_pre[RT_THREADS][NE];
    __shared__ int s_total[NE];
    __shared__ int s_exoff[NE];

    const int tid = threadIdx.x;
    const int warp = tid >> 5, lane = tid & 31;

    int loc[NE];
#pragma unroll
    for (int e = 0; e < NE; e++) loc[e] = 0;
    int eid[RT_PER_THR];
#pragma unroll
    for (int i = 0; i < RT_PER_THR; i++) {
        int id = token_ids[tid * RT_PER_THR + i];
        id = min(max(id, 0), NVOCAB - 1);
        int e = id & (NE - 1);
        eid[i] = e;
        loc[e]++;
    }
#pragma unroll
    for (int e = 0; e < NE; e++) s_hist[tid][e] = loc[e];
    __syncthreads();

    if (warp < NE) {
        const int e = warp;
        int run = 0;
        for (int c = 0; c < RT_THREADS; c += 32) {
            int orig = s_hist[c + lane][e];
            int v = orig;
#pragma unroll
            for (int d = 1; d < 32; d <<= 1) {
                int n = __shfl_up_sync(0xFFFFFFFFu, v, d);
                if (lane >= d) v += n;
            }
            s_pre[c + lane][e] = run + v - orig;
            run += __shfl_sync(0xFFFFFFFFu, v, 31);
        }
        if (lane == 31) s_total[e] = run;
    }
    __syncthreads();
    if (tid == 0) {
        int off = 0;
        for (int e = 0; e < NE; e++) {
            s_exoff[e] = off;
            g_off[e] = off;
            g_cnt[e] = s_total[e];
            off += s_total[e];
        }
    }
    __syncthreads();
    int cur[NE];
#pragma unroll
    for (int e = 0; e < NE; e++) cur[e] = s_exoff[e] + s_pre[tid][e];
#pragma unroll
    for (int i = 0; i < RT_PER_THR; i++) {
        int e = eid[i];
        g_perm[cur[e]++] = tid * RT_PER_THR + i;
    }
}

// ---------------------------------------------------------------------------
// Activation: g_h = fp16(silu(gate) * up), reading fp16 g_gu
// ---------------------------------------------------------------------------
__global__ __launch_bounds__(256)
void act_kernel() {
    int idx = blockIdx.x * blockDim.x + threadIdx.x;
    int row = idx / (EI / 4);
    int c   = (idx % (EI / 4)) * 4;
    const __half* gu = g_gu + (size_t)row * H;
    uint2 gp = *reinterpret_cast<const uint2*>(gu + c);
    uint2 up = *reinterpret_cast<const uint2*>(gu + c + EI);
    float2 g0 = __half22float2(*reinterpret_cast<__half2*>(&gp.x));
    float2 g1 = __half22float2(*reinterpret_cast<__half2*>(&gp.y));
    float2 u0 = __half22float2(*reinterpret_cast<__half2*>(&up.x));
    float2 u1 = __half22float2(*reinterpret_cast<__half2*>(&up.y));
    uint2 o;
    o.x = pack2h(silu(g0.x) * u0.x, silu(g0.y) * u0.y);
    o.y = pack2h(silu(g1.x) * u1.x, silu(g1.y) * u1.y);
    *reinterpret_cast<uint2*>(g_h + (size_t)row * EI + c) = o;
}

// ---------------------------------------------------------------------------
// GEMM body: C[128,128] = A(fp16 rows) @ W[K][N] (f32 streamed, fragment-pack)
// 512 threads, 16 warps 2M x 8N (warp tile 64x16 -- proven fragment paths).
// 3-stage BK=64 pipeline, stage issued AFTER the barrier (R10/R14 skeleton).
// ---------------------------------------------------------------------------
#define TC_GEMM_BODY(A_SRC_ROW, WP, LDN, KTOT, EPILOGUE)                            \
    extern __shared__ char smc[];                                                   \
    int* s_tok = (int*)(smc + TOK_OFF);                                             \
    const int tid = threadIdx.x;                                                    \
    if (tid < BM) s_tok[tid] = g_perm[min(base + m0 + tid, NT - 1)];                \
    __syncthreads();                                                                \
    const int warp = tid >> 5, lane = tid & 31;                                     \
    const int wm = (warp & 1) * 64;                                                 \
    const int wn = (warp >> 1) * 16;                                                \
    const int grp = lane >> 2, quad = lane & 3;                                     \
    const int a_row = tid >> 3, a_ch = tid & 7;    /* 64 rows/pass, 2 passes */     \
    const int b_row = tid >> 5, b_ch = tid & 31;   /* 16 rows/pass, 4 passes */     \
    const int lm_row = wm + (lane & 15);                                            \
    const int lm_col = (lane >> 4) * 16;                                            \
    float acc[4][2][4];                                                             \
    _Pragma("unroll")                                                               \
    for (int i = 0; i < 4; i++)                                                     \
        _Pragma("unroll")                                                           \
        for (int j = 0; j < 2; j++)                                                 \
            _Pragma("unroll")                                                       \
            for (int r = 0; r < 4; r++) acc[i][j][r] = 0.f;                         \
    auto stage = [&](int kt0, int buf) {                                            \
        char* sa = smc + buf * STAGE_BYTES;                                         \
        char* sb = sa + A_BYTES;                                                    \
        _Pragma("unroll")                                                           \
        for (int i = 0; i < 2; i++) {                                               \
            int row = a_row + i * 64;                                               \
            cp_async16(sa + row * AROWB + a_ch * 16,                                \
                       A_SRC_ROW(row) + kt0 + a_ch * 8);                            \
        }                                                                           \
        _Pragma("unroll")                                                           \
        for (int i = 0; i < 4; i++) {                                               \
            int k = b_row + i * 16;                                                 \
            cp_async16(sb + k * BROWB + b_ch * 16,                                  \
                       (WP) + (size_t)(kt0 + k) * (LDN) + n0 + b_ch * 4);           \
        }                                                                           \
        CP_COMMIT();                                                                \
    };                                                                              \
    const int KT = (KTOT) / BK;                                                     \
    stage(0, 0); stage(BK, 1);                                                      \
    for (int kt = 0; kt < KT; kt++) {                                               \
        if (kt + 1 < KT) { CP_WAIT(1); } else { CP_WAIT(0); }                       \
        __syncthreads();                                                            \
        if (kt + 2 < KT) stage((kt + 2) * BK, (kt + 2) % NSTAGE);                   \
        const char*  sa  = smc + (kt % NSTAGE) * STAGE_BYTES;                       \
        const float* sbf = (const float*)(sa + A_BYTES);                            \
        const uint32_t sa_u = (uint32_t)__cvta_generic_to_shared(sa);               \
        _Pragma("unroll")                                                           \
        for (int ks = 0; ks < 4; ks++) {                                            \
            uint32_t af[4][4], bf[2][2];                                            \
            _Pragma("unroll")                                                       \
            for (int mf = 0; mf < 4; mf++)                                          \
                ldsm_x4(af[mf], sa_u + (uint32_t)((lm_row + mf * 16) * AROWB        \
                                                  + ks * 32 + lm_col));             \
            _Pragma("unroll")                                                       \
            for (int nf = 0; nf < 2; nf++) {                                        \
                int n  = wn + nf * 8 + grp;                                         \
                int k0 = ks * 16 + quad * 2;                                        \
                bf[nf][0] = pack2h(sbf[(size_t)k0 * 132 + n],                       \
                                   sbf[(size_t)(k0 + 1) * 132 + n]);                \
                bf[nf][1] = pack2h(sbf[(size_t)(k0 + 8) * 132 + n],                 \
                                   sbf[(size_t)(k0 + 9) * 132 + n]);                \
            }                                                                       \
            _Pragma("unroll")                                                       \
            for (int mf = 0; mf < 4; mf++)                                          \
                _Pragma("unroll")                                                   \
                for (int nf = 0; nf < 2; nf++)                                      \
                    mma_f16(acc[mf][nf], af[mf], bf[nf]);                           \
        }                                                                           \
    }                                                                               \
    const int mrem = cnt - m0;                                                      \
    _Pragma("unroll")                                                               \
    for (int mf = 0; mf < 4; mf++) {                                                \
        int r0 = wm + mf * 16 + grp;                                                \
        int r1 = r0 + 8;                                                            \
        _Pragma("unroll")                                                           \
        for (int nf = 0; nf < 2; nf++) {                                            \
            int c = n0 + wn + nf * 8 + quad * 2;                                    \
            EPILOGUE                                                                \
        }                                                                           \
    }

// GEMM1: g_gu[base+m0+r, :] = xh(token rows) @ gate_up[e]   (K=H, N=2*EI)
__global__ __launch_bounds__(NTHR, 1)
void gemm1_kernel(const float* __restrict__ gate_up) {
    const int e   = blockIdx.z;
    const int cnt = g_cnt[e];
    const int m0  = blockIdx.y * BM;
    if (m0 >= cnt) return;
    const int base = g_off[e];
    const int n0   = blockIdx.x * BN;
    const float* Wp = gate_up + (size_t)e * H * (2 * EI);

#define A1_SRC(row) (g_xh + (size_t)s_tok[row] * H)
#define EPI1                                                                        \
    if (r0 < mrem)                                                                  \
        *reinterpret_cast<uint32_t*>(&g_gu[(size_t)(base + m0 + r0) * H + c]) =     \
            pack2h(acc[mf][nf][0], acc[mf][nf][1]);                                 \
    if (r1 < mrem)                                                                  \
        *reinterpret_cast<uint32_t*>(&g_gu[(size_t)(base + m0 + r1) * H + c]) =     \
            pack2h(acc[mf][nf][2], acc[mf][nf][3]);

    TC_GEMM_BODY(A1_SRC, Wp, 2 * EI, H, EPI1)
#undef A1_SRC
#undef EPI1
}

// GEMM2: out[tok, :] = g_h(sorted rows) @ down[e]   (K=EI, N=H)
__global__ __launch_bounds__(NTHR, 1)
void gemm2_kernel(const float* __restrict__ down, float* __restrict__ out) {
    const int e   = blockIdx.z;
    const int cnt = g_cnt[e];
    const int m0  = blockIdx.y * BM;
    if (m0 >= cnt) return;
    const int base = g_off[e];
    const int n0   = blockIdx.x * BN;
    const float* Wp = down + (size_t)e * EI * H;

#define A2_SRC(row) (g_h + (size_t)min(base + m0 + (row), NT - 1) * EI)
#define EPI2                                                                        \
    if (r0 < mrem)                                                                  \
        *reinterpret_cast<float2*>(&out[(size_t)s_tok[r0] * H + c]) =               \
            make_float2(acc[mf][nf][0], acc[mf][nf][1]);                            \
    if (r1 < mrem)                                                                  \
        *reinterpret_cast<float2*>(&out[(size_t)s_tok[r1] * H + c]) =               \
            make_float2(acc[mf][nf][2], acc[mf][nf][3]);

    TC_GEMM_BODY(A2_SRC, Wp, H, EI, EPI2)
#undef A2_SRC
#undef EPI2
}

// ---------------------------------------------------------------------------
// Launch
// ---------------------------------------------------------------------------
extern "C" void kernel_launch(void* const* d_in, const int* in_sizes, int n_in,
                              void* d_out, int out_size) {
    const float* x         = (const float*)d_in[0];
    const int*   token_ids = (const int*)d_in[1];
    const float* gate_up   = (const float*)d_in[2];
    const float* down      = (const float*)d_in[3];
    float*       out       = (float*)d_out;

    cudaFuncSetAttribute(gemm1_kernel, cudaFuncAttributeMaxDynamicSharedMemorySize, SMEM_BYTES);
    cudaFuncSetAttribute(gemm2_kernel, cudaFuncAttributeMaxDynamicSharedMemorySize, SMEM_BYTES);

    prep_kernel<<<NXB + 1, 256>>>(x, token_ids);

    dim3 grid1(2 * EI / BN, NT / BM, NE);   // 16 x 16 x 8
    gemm1_kernel<<<grid1, NTHR, SMEM_BYTES>>>(gate_up);
    act_kernel<<<(NT * EI / 4) / 256, 256>>>();
    dim3 grid2(H / BN, NT / BM, NE);        // 16 x 16 x 8
    gemm2_kernel<<<grid2, NTHR, SMEM_BYTES>>>(down, out);
}

// round 16
// speedup vs baseline: 1.0484x; 1.0484x over previous
#include <cuda_runtime.h>
#include <cuda_fp16.h>
#include <cstdint>

// Problem constants
#define H      2048
#define EI     1024
#define NE     8
#define NT     2048
#define NVOCAB 32000

// GEMM tiling: 128 x 64 tile, BK = 64 k per stage, 8 warps (2M x 4N)
#define BM 128
#define BN 64
#define BK 64

// smem per stage: A fp16 [128][64] stride 144B, B f32 [64][64] stride 272B
#define AROWB 144
#define BROWB 272
#define A_BYTES (128 * AROWB)            // 18432
#define B_BYTES (64 * BROWB)             // 17408
#define STAGE_BYTES (A_BYTES + B_BYTES)  // 35840
#define NSTAGE 3
#define TOK_OFF (NSTAGE * STAGE_BYTES)   // 107520
#define SMEM_BYTES (TOK_OFF + BM * 4)    // 108032 -> 2 CTAs/SM

// Scratch (12 MB)
__device__ __half g_xh[(size_t)NT * H];
__device__ __half g_h[(size_t)NT * EI];
__device__ int    g_perm[NT];
__device__ int    g_cnt[NE];
__device__ int    g_off[NE];

// ---------------------------------------------------------------------------
// helpers
// ---------------------------------------------------------------------------
__device__ __forceinline__ float silu(float x) { return x / (1.0f + __expf(-x)); }

__device__ __forceinline__ void cp_async16(void* dst_smem, const void* src) {
    uint32_t dst = (uint32_t)__cvta_generic_to_shared(dst_smem);
    asm volatile("cp.async.cg.shared.global [%0], [%1], 16;\n" :: "r"(dst), "l"(src));
}
#define CP_COMMIT() asm volatile("cp.async.commit_group;\n")
#define CP_WAIT(n)  asm volatile("cp.async.wait_group %0;\n" :: "n"(n))

__device__ __forceinline__ void mma_f16(float* d, const uint32_t* a, const uint32_t* b) {
    asm volatile(
        "mma.sync.aligned.m16n8k16.row.col.f32.f16.f16.f32 "
        "{%0,%1,%2,%3}, {%4,%5,%6,%7}, {%8,%9}, {%0,%1,%2,%3};"
        : "+f"(d[0]), "+f"(d[1]), "+f"(d[2]), "+f"(d[3])
        : "r"(a[0]), "r"(a[1]), "r"(a[2]), "r"(a[3]), "r"(b[0]), "r"(b[1]));
}

__device__ __forceinline__ void ldsm_x4(uint32_t* r, uint32_t addr) {
    asm volatile("ldmatrix.sync.aligned.m8n8.x4.shared.b16 {%0,%1,%2,%3}, [%4];"
                 : "=r"(r[0]), "=r"(r[1]), "=r"(r[2]), "=r"(r[3]) : "r"(addr));
}

__device__ __forceinline__ uint32_t pack2h(float lo, float hi) {
    __half2 h = __floats2half2_rn(lo, hi);
    return *reinterpret_cast<uint32_t*>(&h);
}

// ---------------------------------------------------------------------------
// prep: blocks [0, NXB) convert x -> fp16; block NXB does routing.
// ---------------------------------------------------------------------------
#define RT_THREADS 256
#define RT_PER_THR (NT / RT_THREADS)
#define NXB ((NT * H / 8) / 256)

__global__ void prep_kernel(const float* __restrict__ x,
                            const int* __restrict__ token_ids) {
    if (blockIdx.x < NXB) {
        size_t i = ((size_t)blockIdx.x * 256 + threadIdx.x) * 8;
        float4 v0 = *reinterpret_cast<const float4*>(x + i);
        float4 v1 = *reinterpret_cast<const float4*>(x + i + 4);
        uint4 u;
        u.x = pack2h(v0.x, v0.y);
        u.y = pack2h(v0.z, v0.w);
        u.z = pack2h(v1.x, v1.y);
        u.w = pack2h(v1.z, v1.w);
        *reinterpret_cast<uint4*>(g_xh + i) = u;
        return;
    }

    __shared__ int s_hist[RT_THREADS][NE];
    __shared__ int s_pre[RT_THREADS][NE];
    __shared__ int s_total[NE];
    __shared__ int s_exoff[NE];

    const int tid = threadIdx.x;
    const int warp = tid >> 5, lane = tid & 31;

    int loc[NE];
#pragma unroll
    for (int e = 0; e < NE; e++) loc[e] = 0;
    int eid[RT_PER_THR];
#pragma unroll
    for (int i = 0; i < RT_PER_THR; i++) {
        int id = token_ids[tid * RT_PER_THR + i];
        id = min(max(id, 0), NVOCAB - 1);
        int e = id & (NE - 1);
        eid[i] = e;
        loc[e]++;
    }
#pragma unroll
    for (int e = 0; e < NE; e++) s_hist[tid][e] = loc[e];
    __syncthreads();

    if (warp < NE) {
        const int e = warp;
        int run = 0;
        for (int c = 0; c < RT_THREADS; c += 32) {
            int orig = s_hist[c + lane][e];
            int v = orig;
#pragma unroll
            for (int d = 1; d < 32; d <<= 1) {
                int n = __shfl_up_sync(0xFFFFFFFFu, v, d);
                if (lane >= d) v += n;
            }
            s_pre[c + lane][e] = run + v - orig;
            run += __shfl_sync(0xFFFFFFFFu, v, 31);
        }
        if (lane == 31) s_total[e] = run;
    }
    __syncthreads();
    if (tid == 0) {
        int off = 0;
        for (int e = 0; e < NE; e++) {
            s_exoff[e] = off;
            g_off[e] = off;
            g_cnt[e] = s_total[e];
            off += s_total[e];
        }
    }
    __syncthreads();
    int cur[NE];
#pragma unroll
    for (int e = 0; e < NE; e++) cur[e] = s_exoff[e] + s_pre[tid][e];
#pragma unroll
    for (int i = 0; i < RT_PER_THR; i++) {
        int e = eid[i];
        g_perm[cur[e]++] = tid * RT_PER_THR + i;
    }
}

// ---------------------------------------------------------------------------
// GEMM body (R14 skeleton): C[128,64] = A(fp16 rows) @ W cols (f32 streamed).
// 3-stage BK=64 pipeline, stage issued AFTER the barrier. A via ldmatrix.x4,
// B via scalar LDS + pack. B_COL maps smem col -> global col (allows the
// gate/up interleave in gemm1). EPILOGUE sees acc/mf/nf/r0/r1/c/mrem.
// ---------------------------------------------------------------------------
#define TC_GEMM_BODY(A_SRC_ROW, WP, LDN, B_COL, KTOT, EPILOGUE)                     \
    extern __shared__ char smc[];                                                   \
    int* s_tok = (int*)(smc + TOK_OFF);                                             \
    const int tid = threadIdx.x;                                                    \
    if (tid < BM) s_tok[tid] = g_perm[min(base + m0 + tid, NT - 1)];                \
    __syncthreads();                                                                \
    const int warp = tid >> 5, lane = tid & 31;                                     \
    const int wm = (warp & 1) * 64;                                                 \
    const int wn = (warp >> 1) * 16;                                                \
    const int grp = lane >> 2, quad = lane & 3;                                     \
    const int a_row = tid >> 3, a_ch = tid & 7;                                     \
    const int b_row = tid >> 4, b_ch = tid & 15;                                    \
    const int lm_row = wm + (lane & 15);                                            \
    const int lm_col = (lane >> 4) * 16;                                            \
    float acc[4][2][4];                                                             \
    _Pragma("unroll")                                                               \
    for (int i = 0; i < 4; i++)                                                     \
        _Pragma("unroll")                                                           \
        for (int j = 0; j < 2; j++)                                                 \
            _Pragma("unroll")                                                       \
            for (int r = 0; r < 4; r++) acc[i][j][r] = 0.f;                         \
    auto stage = [&](int kt0, int buf) {                                            \
        char* sa = smc + buf * STAGE_BYTES;                                         \
        char* sb = sa + A_BYTES;                                                    \
        _Pragma("unroll")                                                           \
        for (int i = 0; i < 4; i++) {                                               \
            int row = a_row + i * 32;                                               \
            cp_async16(sa + row * AROWB + a_ch * 16,                                \
                       A_SRC_ROW(row) + kt0 + a_ch * 8);                            \
        }                                                                           \
        _Pragma("unroll")                                                           \
        for (int i = 0; i < 4; i++) {                                               \
            int k  = b_row + i * 16;                                                \
            int c0 = b_ch * 4;                                                      \
            cp_async16(sb + k * BROWB + b_ch * 16,                                  \
                       (WP) + (size_t)(kt0 + k) * (LDN) + (B_COL(c0)));             \
        }                                                                           \
        CP_COMMIT();                                                                \
    };                                                                              \
    const int KT = (KTOT) / BK;                                                     \
    stage(0, 0); stage(BK, 1);                                                      \
    for (int kt = 0; kt < KT; kt++) {                                               \
        if (kt + 1 < KT) { CP_WAIT(1); } else { CP_WAIT(0); }                       \
        __syncthreads();                                                            \
        if (kt + 2 < KT) stage((kt + 2) * BK, (kt + 2) % NSTAGE);                   \
        const char*  sa  = smc + (kt % NSTAGE) * STAGE_BYTES;                       \
        const float* sbf = (const float*)(sa + A_BYTES);                            \
        const uint32_t sa_u = (uint32_t)__cvta_generic_to_shared(sa);               \
        _Pragma("unroll")                                                           \
        for (int ks = 0; ks < 4; ks++) {                                            \
            uint32_t af[4][4], bf[2][2];                                            \
            _Pragma("unroll")                                                       \
            for (int mf = 0; mf < 4; mf++)                                          \
                ldsm_x4(af[mf], sa_u + (uint32_t)((lm_row + mf * 16) * AROWB        \
                                                  + ks * 32 + lm_col));             \
            _Pragma("unroll")                                                       \
            for (int nf = 0; nf < 2; nf++) {                                        \
                int n  = wn + nf * 8 + grp;                                         \
                int k0 = ks * 16 + quad * 2;                                        \
                bf[nf][0] = pack2h(sbf[(size_t)k0 * 68 + n],                        \
                                   sbf[(size_t)(k0 + 1) * 68 + n]);                 \
                bf[nf][1] = pack2h(sbf[(size_t)(k0 + 8) * 68 + n],                  \
                                   sbf[(size_t)(k0 + 9) * 68 + n]);                 \
            }                                                                       \
            _Pragma("unroll")                                                       \
            for (int mf = 0; mf < 4; mf++)                                          \
                _Pragma("unroll")                                                   \
                for (int nf = 0; nf < 2; nf++)                                      \
                    mma_f16(acc[mf][nf], af[mf], bf[nf]);                           \
        }                                                                           \
    }                                                                               \
    const int mrem = cnt - m0;                                                      \
    _Pragma("unroll")                                                               \
    for (int mf = 0; mf < 4; mf++) {                                                \
        int r0 = wm + mf * 16 + grp;                                                \
        int r1 = r0 + 8;                                                            \
        _Pragma("unroll")                                                           \
        for (int nf = 0; nf < 2; nf++) {                                            \
            int c = n0 + wn + nf * 8 + quad * 2;                                    \
            (void)c;                                                                \
            EPILOGUE                                                                \
        }                                                                           \
    }

// ---------------------------------------------------------------------------
// GEMM1 (fused activation): each CTA covers 32 logical gate/up column pairs.
// B smem cols: [16w, 16w+8) = gate cols n0+8w.. ; [16w+8, 16w+16) = matching
// up cols (+EI). Warp wn=16w then has acc[..][0]=gate, acc[..][1]=up at the
// SAME logical column -> silu fused in registers; writes g_h fp16 directly.
// ---------------------------------------------------------------------------
__global__ __launch_bounds__(256, 2)
void gemm1_kernel(const float* __restrict__ gate_up) {
    const int e   = blockIdx.z;
    const int cnt = g_cnt[e];
    const int m0  = blockIdx.y * BM;
    if (m0 >= cnt) return;
    const int base = g_off[e];
    const int n0   = blockIdx.x * 32;     // logical (paired) column base
    const float* Wp = gate_up + (size_t)e * H * (2 * EI);

#define A1_SRC(row) (g_xh + (size_t)s_tok[row] * H)
#define B1_COL(c0) (n0 + (((c0) >> 4) << 3) + ((c0) & 7) + ((((c0) >> 3) & 1) * EI))
#define EPI1                                                                        \
    if (nf == 0) {                                                                  \
        int hc = n0 + ((warp >> 1) << 3) + quad * 2;                                \
        if (r0 < mrem) {                                                            \
            float h0 = silu(acc[mf][0][0]) * acc[mf][1][0];                         \
            float h1 = silu(acc[mf][0][1]) * acc[mf][1][1];                         \
            *reinterpret_cast<uint32_t*>(                                           \
                &g_h[(size_t)(base + m0 + r0) * EI + hc]) = pack2h(h0, h1);         \
        }                                                                           \
        if (r1 < mrem) {                                                            \
            float h2 = silu(acc[mf][0][2]) * acc[mf][1][2];                         \
            float h3 = silu(acc[mf][0][3]) * acc[mf][1][3];                         \
            *reinterpret_cast<uint32_t*>(                                           \
                &g_h[(size_t)(base + m0 + r1) * EI + hc]) = pack2h(h2, h3);         \
        }                                                                           \
    }

    TC_GEMM_BODY(A1_SRC, Wp, 2 * EI, B1_COL, H, EPI1)
#undef A1_SRC
#undef B1_COL
#undef EPI1
}

// ---------------------------------------------------------------------------
// GEMM2: out[tok, :] = g_h(sorted rows) @ down[e]   (K=EI, N=H)
// ---------------------------------------------------------------------------
__global__ __launch_bounds__(256, 2)
void gemm2_kernel(const float* __restrict__ down, float* __restrict__ out) {
    const int e   = blockIdx.z;
    const int cnt = g_cnt[e];
    const int m0  = blockIdx.y * BM;
    if (m0 >= cnt) return;
    const int base = g_off[e];
    const int n0   = blockIdx.x * BN;
    const float* Wp = down + (size_t)e * EI * H;

#define A2_SRC(row) (g_h + (size_t)min(base + m0 + (row), NT - 1) * EI)
#define B2_COL(c0) (n0 + (c0))
#define EPI2                                                                        \
    if (r0 < mrem)                                                                  \
        *reinterpret_cast<float2*>(&out[(size_t)s_tok[r0] * H + c]) =               \
            make_float2(acc[mf][nf][0], acc[mf][nf][1]);                            \
    if (r1 < mrem)                                                                  \
        *reinterpret_cast<float2*>(&out[(size_t)s_tok[r1] * H + c]) =               \
            make_float2(acc[mf][nf][2], acc[mf][nf][3]);

    TC_GEMM_BODY(A2_SRC, Wp, H, B2_COL, EI, EPI2)
#undef A2_SRC
#undef B2_COL
#undef EPI2
}

// ---------------------------------------------------------------------------
// Launch
// ---------------------------------------------------------------------------
extern "C" void kernel_launch(void* const* d_in, const int* in_sizes, int n_in,
                              void* d_out, int out_size) {
    const float* x         = (const float*)d_in[0];
    const int*   token_ids = (const int*)d_in[1];
    const float* gate_up   = (const float*)d_in[2];
    const float* down      = (const float*)d_in[3];
    float*       out       = (float*)d_out;

    cudaFuncSetAttribute(gemm1_kernel, cudaFuncAttributeMaxDynamicSharedMemorySize, SMEM_BYTES);
    cudaFuncSetAttribute(gemm2_kernel, cudaFuncAttributeMaxDynamicSharedMemorySize, SMEM_BYTES);

    prep_kernel<<<NXB + 1, 256>>>(x, token_ids);

    dim3 grid1(EI / 32, NT / BM, NE);   // 32 x 16 x 8 (paired gate/up columns)
    gemm1_kernel<<<grid1, 256, SMEM_BYTES>>>(gate_up);
    dim3 grid2(H / BN, NT / BM, NE);    // 32 x 16 x 8
    gemm2_kernel<<<grid2, 256, SMEM_BYTES>>>(down, out);
}

// round 17
// speedup vs baseline: 1.2041x; 1.1486x over previous
#include <cuda_runtime.h>
#include <cuda_fp16.h>
#include <cstdint>

// Problem constants
#define H      2048
#define EI     1024
#define NE     8
#define NT     2048
#define NVOCAB 32000

// GEMM tiling: 128 x 64 tile, BK = 64 k per stage, 8 warps (2M x 4N)
#define BM 128
#define BN 64
#define BK 64

// smem per stage: A fp16 [128][64] stride 144B, B f32 [64][64] stride 272B
#define AROWB 144
#define BROWB 272
#define A_BYTES (128 * AROWB)            // 18432
#define B_BYTES (64 * BROWB)             // 17408
#define STAGE_BYTES (A_BYTES + B_BYTES)  // 35840
#define NSTAGE 3
#define TOK_OFF (NSTAGE * STAGE_BYTES)   // 107520
#define SMEM_BYTES (TOK_OFF + BM * 4)    // 108032 -> 2 CTAs/SM

// Scratch (12 MB)
__device__ __half g_xh[(size_t)NT * H];
__device__ __half g_h[(size_t)NT * EI];
__device__ int    g_perm[NT];
__device__ int    g_cnt[NE];
__device__ int    g_off[NE];

// ---------------------------------------------------------------------------
// helpers
// ---------------------------------------------------------------------------
__device__ __forceinline__ float silu(float x) { return x / (1.0f + __expf(-x)); }

__device__ __forceinline__ void cp_async16(void* dst_smem, const void* src) {
    uint32_t dst = (uint32_t)__cvta_generic_to_shared(dst_smem);
    asm volatile("cp.async.cg.shared.global [%0], [%1], 16;\n" :: "r"(dst), "l"(src));
}
#define CP_COMMIT() asm volatile("cp.async.commit_group;\n")
#define CP_WAIT(n)  asm volatile("cp.async.wait_group %0;\n" :: "n"(n))

__device__ __forceinline__ void mma_f16(float* d, const uint32_t* a, const uint32_t* b) {
    asm volatile(
        "mma.sync.aligned.m16n8k16.row.col.f32.f16.f16.f32 "
        "{%0,%1,%2,%3}, {%4,%5,%6,%7}, {%8,%9}, {%0,%1,%2,%3};"
        : "+f"(d[0]), "+f"(d[1]), "+f"(d[2]), "+f"(d[3])
        : "r"(a[0]), "r"(a[1]), "r"(a[2]), "r"(a[3]), "r"(b[0]), "r"(b[1]));
}

__device__ __forceinline__ void ldsm_x4(uint32_t* r, uint32_t addr) {
    asm volatile("ldmatrix.sync.aligned.m8n8.x4.shared.b16 {%0,%1,%2,%3}, [%4];"
                 : "=r"(r[0]), "=r"(r[1]), "=r"(r[2]), "=r"(r[3]) : "r"(addr));
}

__device__ __forceinline__ uint32_t pack2h(float lo, float hi) {
    __half2 h = __floats2half2_rn(lo, hi);
    return *reinterpret_cast<uint32_t*>(&h);
}

// ---------------------------------------------------------------------------
// prep: blocks [0, NXB) convert x -> fp16; block NXB does routing.
// ---------------------------------------------------------------------------
#define RT_THREADS 256
#define RT_PER_THR (NT / RT_THREADS)
#define NXB ((NT * H / 8) / 256)

__global__ void prep_kernel(const float* __restrict__ x,
                            const int* __restrict__ token_ids) {
    if (blockIdx.x < NXB) {
        size_t i = ((size_t)blockIdx.x * 256 + threadIdx.x) * 8;
        float4 v0 = *reinterpret_cast<const float4*>(x + i);
        float4 v1 = *reinterpret_cast<const float4*>(x + i + 4);
        uint4 u;
        u.x = pack2h(v0.x, v0.y);
        u.y = pack2h(v0.z, v0.w);
        u.z = pack2h(v1.x, v1.y);
        u.w = pack2h(v1.z, v1.w);
        *reinterpret_cast<uint4*>(g_xh + i) = u;
        return;
    }

    __shared__ int s_hist[RT_THREADS][NE];
    __shared__ int s_pre[RT_THREADS][NE];
    __shared__ int s_total[NE];
    __shared__ int s_exoff[NE];

    const int tid = threadIdx.x;
    const int warp = tid >> 5, lane = tid & 31;

    int loc[NE];
#pragma unroll
    for (int e = 0; e < NE; e++) loc[e] = 0;
    int eid[RT_PER_THR];
#pragma unroll
    for (int i = 0; i < RT_PER_THR; i++) {
        int id = token_ids[tid * RT_PER_THR + i];
        id = min(max(id, 0), NVOCAB - 1);
        int e = id & (NE - 1);
        eid[i] = e;
        loc[e]++;
    }
#pragma unroll
    for (int e = 0; e < NE; e++) s_hist[tid][e] = loc[e];
    __syncthreads();

    if (warp < NE) {
        const int e = warp;
        int run = 0;
        for (int c = 0; c < RT_THREADS; c += 32) {
            int orig = s_hist[c + lane][e];
            int v = orig;
#pragma unroll
            for (int d = 1; d < 32; d <<= 1) {
                int n = __shfl_up_sync(0xFFFFFFFFu, v, d);
                if (lane >= d) v += n;
            }
            s_pre[c + lane][e] = run + v - orig;
            run += __shfl_sync(0xFFFFFFFFu, v, 31);
        }
        if (lane == 31) s_total[e] = run;
    }
    __syncthreads();
    if (tid == 0) {
        int off = 0;
        for (int e = 0; e < NE; e++) {
            s_exoff[e] = off;
            g_off[e] = off;
            g_cnt[e] = s_total[e];
            off += s_total[e];
        }
    }
    __syncthreads();
    int cur[NE];
#pragma unroll
    for (int e = 0; e < NE; e++) cur[e] = s_exoff[e] + s_pre[tid][e];
#pragma unroll
    for (int i = 0; i < RT_PER_THR; i++) {
        int e = eid[i];
        g_perm[cur[e]++] = tid * RT_PER_THR + i;
    }
}

// ---------------------------------------------------------------------------
// GEMM body (R14 skeleton): C[128,64] = A(fp16 rows) @ W cols (f32 streamed).
// 3-stage BK=64 pipeline, stage issued AFTER the barrier. A via ldmatrix.x4,
// B via scalar LDS + pack.
//  B_COL(c0): smem col -> global col (c0 in 4-col granules, contiguous in
//  blocks of >=32 cols so global requests stay 128B-coalesced).
//  WN_STEP: warp n-stride; NF_STEP: smem-col offset between nf=0 and nf=1.
// ---------------------------------------------------------------------------
#define TC_GEMM_BODY(A_SRC_ROW, WP, LDN, B_COL, WN_STEP, NF_STEP, KTOT, EPILOGUE)   \
    extern __shared__ char smc[];                                                   \
    int* s_tok = (int*)(smc + TOK_OFF);                                             \
    const int tid = threadIdx.x;                                                    \
    if (tid < BM) s_tok[tid] = g_perm[min(base + m0 + tid, NT - 1)];                \
    __syncthreads();                                                                \
    const int warp = tid >> 5, lane = tid & 31;                                     \
    const int wm = (warp & 1) * 64;                                                 \
    const int wn = (warp >> 1) * (WN_STEP);                                         \
    const int grp = lane >> 2, quad = lane & 3;                                     \
    const int a_row = tid >> 3, a_ch = tid & 7;                                     \
    const int b_row = tid >> 4, b_ch = tid & 15;                                    \
    const int lm_row = wm + (lane & 15);                                            \
    const int lm_col = (lane >> 4) * 16;                                            \
    float acc[4][2][4];                                                             \
    _Pragma("unroll")                                                               \
    for (int i = 0; i < 4; i++)                                                     \
        _Pragma("unroll")                                                           \
        for (int j = 0; j < 2; j++)                                                 \
            _Pragma("unroll")                                                       \
            for (int r = 0; r < 4; r++) acc[i][j][r] = 0.f;                         \
    auto stage = [&](int kt0, int buf) {                                            \
        char* sa = smc + buf * STAGE_BYTES;                                         \
        char* sb = sa + A_BYTES;                                                    \
        _Pragma("unroll")                                                           \
        for (int i = 0; i < 4; i++) {                                               \
            int row = a_row + i * 32;                                               \
            cp_async16(sa + row * AROWB + a_ch * 16,                                \
                       A_SRC_ROW(row) + kt0 + a_ch * 8);                            \
        }                                                                           \
        _Pragma("unroll")                                                           \
        for (int i = 0; i < 4; i++) {                                               \
            int k  = b_row + i * 16;                                                \
            int c0 = b_ch * 4;                                                      \
            cp_async16(sb + k * BROWB + b_ch * 16,                                  \
                       (WP) + (size_t)(kt0 + k) * (LDN) + (B_COL(c0)));             \
        }                                                                           \
        CP_COMMIT();                                                                \
    };                                                                              \
    const int KT = (KTOT) / BK;                                                     \
    stage(0, 0); stage(BK, 1);                                                      \
    for (int kt = 0; kt < KT; kt++) {                                               \
        if (kt + 1 < KT) { CP_WAIT(1); } else { CP_WAIT(0); }                       \
        __syncthreads();                                                            \
        if (kt + 2 < KT) stage((kt + 2) * BK, (kt + 2) % NSTAGE);                   \
        const char*  sa  = smc + (kt % NSTAGE) * STAGE_BYTES;                       \
        const float* sbf = (const float*)(sa + A_BYTES);                            \
        const uint32_t sa_u = (uint32_t)__cvta_generic_to_shared(sa);               \
        _Pragma("unroll")                                                           \
        for (int ks = 0; ks < 4; ks++) {                                            \
            uint32_t af[4][4], bf[2][2];                                            \
            _Pragma("unroll")                                                       \
            for (int mf = 0; mf < 4; mf++)                                          \
                ldsm_x4(af[mf], sa_u + (uint32_t)((lm_row + mf * 16) * AROWB        \
                                                  + ks * 32 + lm_col));             \
            _Pragma("unroll")                                                       \
            for (int nf = 0; nf < 2; nf++) {                                        \
                int n  = wn + nf * (NF_STEP) + grp;                                 \
                int k0 = ks * 16 + quad * 2;                                        \
                bf[nf][0] = pack2h(sbf[(size_t)k0 * 68 + n],                        \
                                   sbf[(size_t)(k0 + 1) * 68 + n]);                 \
                bf[nf][1] = pack2h(sbf[(size_t)(k0 + 8) * 68 + n],                  \
                                   sbf[(size_t)(k0 + 9) * 68 + n]);                 \
            }                                                                       \
            _Pragma("unroll")                                                       \
            for (int mf = 0; mf < 4; mf++)                                          \
                _Pragma("unroll")                                                   \
                for (int nf = 0; nf < 2; nf++)                                      \
                    mma_f16(acc[mf][nf], af[mf], bf[nf]);                           \
        }                                                                           \
    }                                                                               \
    const int mrem = cnt - m0;                                                      \
    _Pragma("unroll")                                                               \
    for (int mf = 0; mf < 4; mf++) {                                                \
        int r0 = wm + mf * 16 + grp;                                                \
        int r1 = r0 + 8;                                                            \
        _Pragma("unroll")                                                           \
        for (int nf = 0; nf < 2; nf++) {                                            \
            EPILOGUE                                                                \
        }                                                                           \
    }

// ---------------------------------------------------------------------------
// GEMM1 (fused activation, coalesced): B smem = [gate n0..n0+31 | up n0..n0+31]
// (two contiguous 32-col blocks -> 128B-coalesced global loads). Warp layout
// wn=(warp>>1)*8, nf offset 32 -> acc[mf][0]=gate, acc[mf][1]=up at the SAME
// logical column. silu*up fused in registers; writes g_h fp16 directly.
// ---------------------------------------------------------------------------
__global__ __launch_bounds__(256, 2)
void gemm1_kernel(const float* __restrict__ gate_up) {
    const int e   = blockIdx.z;
    const int cnt = g_cnt[e];
    const int m0  = blockIdx.y * BM;
    if (m0 >= cnt) return;
    const int base = g_off[e];
    const int n0   = blockIdx.x * 32;     // logical (paired) column base
    const float* Wp = gate_up + (size_t)e * H * (2 * EI);

#define A1_SRC(row) (g_xh + (size_t)s_tok[row] * H)
#define B1_COL(c0) (n0 + ((c0) & 31) + (((c0) >> 5) * EI))
#define EPI1                                                                        \
    if (nf == 0) {                                                                  \
        int hc = n0 + wn + quad * 2;                                                \
        if (r0 < mrem) {                                                            \
            float h0 = silu(acc[mf][0][0]) * acc[mf][1][0];                         \
            float h1 = silu(acc[mf][0][1]) * acc[mf][1][1];                         \
            *reinterpret_cast<uint32_t*>(                                           \
                &g_h[(size_t)(base + m0 + r0) * EI + hc]) = pack2h(h0, h1);         \
        }                                                                           \
        if (r1 < mrem) {                                                            \
            float h2 = silu(acc[mf][0][2]) * acc[mf][1][2];                         \
            float h3 = silu(acc[mf][0][3]) * acc[mf][1][3];                         \
            *reinterpret_cast<uint32_t*>(                                           \
                &g_h[(size_t)(base + m0 + r1) * EI + hc]) = pack2h(h2, h3);         \
        }                                                                           \
    }

    TC_GEMM_BODY(A1_SRC, Wp, 2 * EI, B1_COL, 8, 32, H, EPI1)
#undef A1_SRC
#undef B1_COL
#undef EPI1
}

// ---------------------------------------------------------------------------
// GEMM2: out[tok, :] = g_h(sorted rows) @ down[e]   (K=EI, N=H)
// ---------------------------------------------------------------------------
__global__ __launch_bounds__(256, 2)
void gemm2_kernel(const float* __restrict__ down, float* __restrict__ out) {
    const int e   = blockIdx.z;
    const int cnt = g_cnt[e];
    const int m0  = blockIdx.y * BM;
    if (m0 >= cnt) return;
    const int base = g_off[e];
    const int n0   = blockIdx.x * BN;
    const float* Wp = down + (size_t)e * EI * H;

#define A2_SRC(row) (g_h + (size_t)min(base + m0 + (row), NT - 1) * EI)
#define B2_COL(c0) (n0 + (c0))
#define EPI2                                                                        \
    {                                                                               \
        int c = n0 + wn + nf * 8 + quad * 2;                                        \
        if (r0 < mrem)                                                              \
            *reinterpret_cast<float2*>(&out[(size_t)s_tok[r0] * H + c]) =           \
                make_float2(acc[mf][nf][0], acc[mf][nf][1]);                        \
        if (r1 < mrem)                                                              \
            *reinterpret_cast<float2*>(&out[(size_t)s_tok[r1] * H + c]) =           \
                make_float2(acc[mf][nf][2], acc[mf][nf][3]);                        \
    }

    TC_GEMM_BODY(A2_SRC, Wp, H, B2_COL, 16, 8, EI, EPI2)
#undef A2_SRC
#undef B2_COL
#undef EPI2
}

// ---------------------------------------------------------------------------
// Launch
// ---------------------------------------------------------------------------
extern "C" void kernel_launch(void* const* d_in, const int* in_sizes, int n_in,
                              void* d_out, int out_size) {
    const float* x         = (const float*)d_in[0];
    const int*   token_ids = (const int*)d_in[1];
    const float* gate_up   = (const float*)d_in[2];
    const float* down      = (const float*)d_in[3];
    float*       out       = (float*)d_out;

    cudaFuncSetAttribute(gemm1_kernel, cudaFuncAttributeMaxDynamicSharedMemorySize, SMEM_BYTES);
    cudaFuncSetAttribute(gemm2_kernel, cudaFuncAttributeMaxDynamicSharedMemorySize, SMEM_BYTES);

    prep_kernel<<<NXB + 1, 256>>>(x, token_ids);

    dim3 grid1(EI / 32, NT / BM, NE);   // 32 x 16 x 8 (paired gate/up columns)
    gemm1_kernel<<<grid1, 256, SMEM_BYTES>>>(gate_up);
    dim3 grid2(H / BN, NT / BM, NE);    // 32 x 16 x 8
    gemm2_kernel<<<grid2, 256, SMEM_BYTES>>>(down, out);
}